// round 8
// baseline (speedup 1.0000x reference)
#include <cuda_runtime.h>
#include <cstdint>

#define EMB     300
#define EMB4    75
#define TASKS   12
#define ROWB    8                       // rows per pipeline chunk
#define NBUF    4
#define THREADS 160                     // 5 warps; 150 loader lanes
#define NCTA    592                     // 4 CTAs/SM x 148 SMs = one wave

__device__ int g_starts[16385 * 2];
__device__ int g_cta_g0[NCTA + 1];      // row-balanced graph ranges per CTA

// ---------------------------------------------------------------------------
// starts[g] = lower_bound(sorted batch, g). int32/int64 detected via word[N-1]
// (int64 high word of last element is 0; int32 last element is max id > 0).
// ---------------------------------------------------------------------------
__global__ void starts_kernel(const void* __restrict__ batch, int N, int G) {
    int i = blockIdx.x * blockDim.x + threadIdx.x;
    if (i >= N) return;
    const int* b32 = (const int*)batch;
    int is64 = (b32[N - 1] == 0);

    long long cur, prev;
    if (is64) {
        const long long* b64 = (const long long*)batch;
        cur  = b64[i];
        prev = (i > 0) ? b64[i - 1] : -1;
    } else {
        cur  = b32[i];
        prev = (i > 0) ? b32[i - 1] : -1;
    }
    for (long long g = prev + 1; g <= cur; ++g) {
        if (g >= 0 && g <= (long long)G) g_starts[g] = i;
    }
    if (i == N - 1) {
        for (long long g = cur + 1; g <= (long long)G; ++g) g_starts[g] = N;
    }
}

// ---------------------------------------------------------------------------
// Row-balanced CTA->graph ranges: cta_g0[i] = lower_bound(starts, i*N/NCTA).
// Forced endpoints ensure complete coverage including trailing empty graphs.
// ---------------------------------------------------------------------------
__global__ void ranges_kernel(int N, int G) {
    int i = blockIdx.x * blockDim.x + threadIdx.x;
    if (i > NCTA) return;
    if (i == 0)        { g_cta_g0[0] = 0;       return; }
    if (i == NCTA)     { g_cta_g0[NCTA] = G;    return; }
    int cut = (int)(((long long)i * N) / NCTA);
    int lo = 0, hi = G;                 // find first g with starts[g] >= cut
    while (lo < hi) {
        int mid = (lo + hi) >> 1;
        if (g_starts[mid] < cut) lo = mid + 1; else hi = mid;
    }
    g_cta_g0[i] = lo;
}

__device__ __forceinline__ void facc(float4& a, const float4 v) {
    a.x += v.x; a.y += v.y; a.z += v.z; a.w += v.w;
}

// ---------------------------------------------------------------------------
// Persistent single-wave CTA over a ROW-BALANCED contiguous graph range: one
// continuous cp.async.bulk stream; per-graph finalize via register-space head
// partials -> double-buffered SMEM -> ONE sync -> 5-warp reduction.
// ---------------------------------------------------------------------------
__global__ __launch_bounds__(THREADS)
void pool_pers_kernel(const float* __restrict__ x,
                      const float* __restrict__ W,
                      const float* __restrict__ b,
                      float* __restrict__ out, int G) {
    __shared__ alignas(16) float4 buf[NBUF][ROWB * EMB4];
    __shared__ alignas(8)  unsigned long long mbar[NBUF];
    __shared__ alignas(16) float sh_part[2][TASKS * THREADS];

    int t = threadIdx.x;
    int g0 = g_cta_g0[blockIdx.x];
    int g1 = g_cta_g0[blockIdx.x + 1];
    int gcnt = g1 - g0;
    if (gcnt <= 0) return;

    int base       = g_starts[g0];
    int rows_total = g_starts[g1] - base;
    int nchunks    = (rows_total + ROWB - 1) / ROWB;

    uint32_t mb0 = (uint32_t)__cvta_generic_to_shared(&mbar[0]);
    if (t == 0) {
        #pragma unroll
        for (int s = 0; s < NBUF; ++s)
            asm volatile("mbarrier.init.shared::cta.b64 [%0], 1;"
                         :: "r"(mb0 + 8u * s) : "memory");
    }
    __syncthreads();

    const char* src_base = (const char*)(x + (size_t)base * EMB);

    if (t == 0) {
        int pre = nchunks < (NBUF - 1) ? nchunks : (NBUF - 1);
        for (int k = 0; k < pre; ++k) {
            int r0 = k * ROWB;
            int rc = rows_total - r0; if (rc > ROWB) rc = ROWB;
            uint32_t bytes = (uint32_t)rc * (EMB * 4);
            uint32_t mb    = mb0 + 8u * k;
            uint32_t dst   = (uint32_t)__cvta_generic_to_shared(&buf[k][0]);
            const char* sp = src_base + (size_t)r0 * (EMB * 4);
            asm volatile("mbarrier.arrive.expect_tx.shared::cta.b64 _, [%0], %1;"
                         :: "r"(mb), "r"(bytes) : "memory");
            asm volatile("cp.async.bulk.shared::cta.global.mbarrier::complete_tx::bytes [%0], [%1], %2, [%3];"
                         :: "r"(dst), "l"(sp), "r"(bytes), "r"(mb) : "memory");
        }
    }

    int c = t % EMB4;            // float4 column (t < 150)
    int p = t / EMB4;            // row parity (t<150)
    int wid = t >> 5, lane = t & 31;
    const float4* __restrict__ W4 = (const float4*)W;
    float4 acc = make_float4(0.f, 0.f, 0.f, 0.f);

    int gi = 0;
    int gstart = 0;
    int nb = g_starts[g0 + 1] - base;

    auto do_finalize = [&](int end_row) {
        int pb = gi & 1;
        #pragma unroll
        for (int task = 0; task < TASKS; ++task) {
            float4 w4 = __ldg(&W4[task * EMB4 + c]);
            sh_part[pb][task * THREADS + t] =
                acc.x * w4.x + acc.y * w4.y + acc.z * w4.z + acc.w * w4.w;
        }
        __syncthreads();
        float inv = 1.0f / fmaxf((float)(end_row - gstart), 1.0f);
        for (int task = wid; task < TASKS; task += 5) {
            const float* sp = &sh_part[pb][task * THREADS];
            float a = sp[lane] + sp[lane + 32] + sp[lane + 64]
                    + sp[lane + 96] + sp[lane + 128];
            #pragma unroll
            for (int o = 16; o; o >>= 1) a += __shfl_xor_sync(0xffffffffu, a, o);
            if (lane == 0)
                out[(size_t)(g0 + gi) * TASKS + task] = a * inv + __ldg(&b[task]);
        }
        acc = make_float4(0.f, 0.f, 0.f, 0.f);
        gstart = end_row;
        ++gi;
        nb = (gi < gcnt) ? g_starts[g0 + gi + 1] - base : 0x7fffffff;
    };

    for (int k = 0; k < nchunks; ++k) {
        int s = k & (NBUF - 1);
        uint32_t mb = mb0 + 8u * s;
        uint32_t ph = (uint32_t)((k >> 2) & 1);

        uint32_t done;
        asm volatile("{\n\t.reg .pred p;\n\t"
                     "mbarrier.try_wait.parity.acquire.cta.shared::cta.b64 p, [%1], %2;\n\t"
                     "selp.b32 %0, 1, 0, p;\n\t}"
                     : "=r"(done) : "r"(mb), "r"(ph) : "memory");
        while (!done) {
            asm volatile("{\n\t.reg .pred p;\n\t"
                         "mbarrier.try_wait.parity.acquire.cta.shared::cta.b64 p, [%1], %2, 0x989680;\n\t"
                         "selp.b32 %0, 1, 0, p;\n\t}"
                         : "=r"(done) : "r"(mb), "r"(ph) : "memory");
        }

        int rbase = k * ROWB;
        int rend  = rbase + ROWB; if (rend > rows_total) rend = rows_total;
        const float4* bp = &buf[s][0];

        if (nb >= rend && rend == rbase + ROWB) {
            if (t < 150) {
                float4 v0 = bp[(0 + p) * EMB4 + c];
                float4 v1 = bp[(2 + p) * EMB4 + c];
                float4 v2 = bp[(4 + p) * EMB4 + c];
                float4 v3 = bp[(6 + p) * EMB4 + c];
                facc(acc, v0); facc(acc, v1); facc(acc, v2); facc(acc, v3);
            }
        } else {
            int pos = rbase;
            while (pos < rend) {
                int stop = nb < rend ? nb : rend;
                if (t < 150) {
                    for (int r = pos; r < stop; ++r) {
                        if (((r - rbase) & 1) == p)
                            facc(acc, bp[(r - rbase) * EMB4 + c]);
                    }
                }
                if (stop == nb) do_finalize(nb);
                pos = stop;
            }
        }
        __syncthreads();   // chunk s consumed -> refill safe

        if (t == 0 && k + (NBUF - 1) < nchunks) {
            asm volatile("fence.proxy.async.shared::cta;" ::: "memory");
            int kk = k + (NBUF - 1);
            int r0 = kk * ROWB;
            int rc = rows_total - r0; if (rc > ROWB) rc = ROWB;
            uint32_t bytes = (uint32_t)rc * (EMB * 4);
            uint32_t mbn   = mb0 + 8u * (kk & (NBUF - 1));
            uint32_t dst   = (uint32_t)__cvta_generic_to_shared(&buf[kk & (NBUF - 1)][0]);
            const char* sp = src_base + (size_t)r0 * (EMB * 4);
            asm volatile("mbarrier.arrive.expect_tx.shared::cta.b64 _, [%0], %1;"
                         :: "r"(mbn), "r"(bytes) : "memory");
            asm volatile("cp.async.bulk.shared::cta.global.mbarrier::complete_tx::bytes [%0], [%1], %2, [%3];"
                         :: "r"(dst), "l"(sp), "r"(bytes), "r"(mbn) : "memory");
        }
    }

    // graph whose boundary coincides with the final chunk end is still open
    if (gi < gcnt) do_finalize(rows_total);

    // remaining graphs are empty: mean = 0 -> out = bias
    while (gi < gcnt) {
        if (t < TASKS) out[(size_t)(g0 + gi) * TASKS + t] = __ldg(&b[t]);
        ++gi;
    }
}

// ---------------------------------------------------------------------------
extern "C" void kernel_launch(void* const* d_in, const int* in_sizes, int n_in,
                              void* d_out, int out_size) {
    const float* x     = (const float*)d_in[0];
    const void*  batch = d_in[1];
    const float* W     = (const float*)d_in[2];
    const float* b     = (const float*)d_in[3];
    float*       out   = (float*)d_out;

    int N = in_sizes[1];
    int G = out_size / TASKS;

    starts_kernel<<<(N + 255) / 256, 256>>>(batch, N, G);
    ranges_kernel<<<3, 256>>>(N, G);
    pool_pers_kernel<<<NCTA, THREADS>>>(x, W, b, out, G);
}

// round 10
// speedup vs baseline: 1.0744x; 1.0744x over previous
#include <cuda_runtime.h>
#include <cstdint>

#define EMB     300
#define EMB4    75
#define TASKS   12
#define ROWB    8                       // rows per pipeline chunk
#define NBUF    4
#define THREADS 160                     // 5 warps; 150 loader lanes
#define NCTA    592                     // 4 CTAs/SM x 148 SMs = one wave

__device__ int g_starts[16385 * 2];

// ---------------------------------------------------------------------------
// Vectorized starts fill: each thread handles 8 consecutive batch elements
// (int4 loads). starts[g] = lower_bound(sorted batch, g).
// int32/int64 detected via word[N-1] (int64 high word == 0).
// ---------------------------------------------------------------------------
__global__ void starts_kernel(const void* __restrict__ batch, int N, int G) {
    int base = (blockIdx.x * blockDim.x + threadIdx.x) * 8;
    if (base >= N) return;
    const int* b32 = (const int*)batch;
    bool is64 = (b32[N - 1] == 0);

    int cnt = N - base; if (cnt > 8) cnt = 8;
    int ids[8];
    if (is64) {
        const long long* b64 = (const long long*)batch;
        if (cnt == 8) {
            const int4* p = (const int4*)(b64 + base);   // 64B-aligned
            int4 v0 = p[0], v1 = p[1], v2 = p[2], v3 = p[3];
            ids[0] = v0.x; ids[1] = v0.z; ids[2] = v1.x; ids[3] = v1.z;
            ids[4] = v2.x; ids[5] = v2.z; ids[6] = v3.x; ids[7] = v3.z;
        } else {
            for (int j = 0; j < cnt; ++j) ids[j] = (int)b64[base + j];
        }
    } else {
        if (cnt == 8) {
            const int4* p = (const int4*)(b32 + base);   // 32B-aligned
            int4 v0 = p[0], v1 = p[1];
            ids[0] = v0.x; ids[1] = v0.y; ids[2] = v0.z; ids[3] = v0.w;
            ids[4] = v1.x; ids[5] = v1.y; ids[6] = v1.z; ids[7] = v1.w;
        } else {
            for (int j = 0; j < cnt; ++j) ids[j] = b32[base + j];
        }
    }

    int prev;
    if (base == 0) prev = -1;
    else prev = is64 ? (int)((const long long*)batch)[base - 1] : b32[base - 1];

    #pragma unroll
    for (int j = 0; j < 8; ++j) {
        if (j >= cnt) break;
        int cur = ids[j];
        for (int g = prev + 1; g <= cur; ++g)
            if (g >= 0 && g <= G) g_starts[g] = base + j;
        prev = cur;
    }
    if (base + cnt == N) {
        for (int g = prev + 1; g <= G; ++g) g_starts[g] = N;
    }
}

__device__ __forceinline__ void facc(float4& a, const float4 v) {
    a.x += v.x; a.y += v.y; a.z += v.z; a.w += v.w;
}

// ---------------------------------------------------------------------------
// Persistent single-wave CTA over a contiguous graph range (graph-count
// split): one continuous cp.async.bulk stream. Finalize: per-thread head
// partial -> warp shfl reduction -> 60-float smem -> ONE sync -> 12 coalesced
// stores. Producer refills 3-ahead immediately after each chunk-wait.
// ---------------------------------------------------------------------------
__global__ __launch_bounds__(THREADS)
void pool_pers_kernel(const float* __restrict__ x,
                      const float* __restrict__ W,
                      const float* __restrict__ b,
                      float* __restrict__ out, int G) {
    __shared__ alignas(16) float4 buf[NBUF][ROWB * EMB4];
    __shared__ alignas(8)  unsigned long long mbar[NBUF];
    __shared__ alignas(16) float sh_warp[2][5 * TASKS];

    int t = threadIdx.x;
    int g0 = (int)(((long long)blockIdx.x * G) / NCTA);
    int g1 = (int)(((long long)(blockIdx.x + 1) * G) / NCTA);
    int gcnt = g1 - g0;
    if (gcnt <= 0) return;

    int base       = g_starts[g0];
    int rows_total = g_starts[g1] - base;
    int nchunks    = (rows_total + ROWB - 1) / ROWB;

    uint32_t mb0 = (uint32_t)__cvta_generic_to_shared(&mbar[0]);
    if (t == 0) {
        #pragma unroll
        for (int s = 0; s < NBUF; ++s)
            asm volatile("mbarrier.init.shared::cta.b64 [%0], 1;"
                         :: "r"(mb0 + 8u * s) : "memory");
    }
    __syncthreads();

    const char* src_base = (const char*)(x + (size_t)base * EMB);

    // producer helper: issue chunk kk into buffer kk & (NBUF-1)
    auto issue = [&](int kk) {
        int r0 = kk * ROWB;
        int rc = rows_total - r0; if (rc > ROWB) rc = ROWB;
        uint32_t bytes = (uint32_t)rc * (EMB * 4);
        uint32_t mb    = mb0 + 8u * (kk & (NBUF - 1));
        uint32_t dst   = (uint32_t)__cvta_generic_to_shared(&buf[kk & (NBUF - 1)][0]);
        const char* sp = src_base + (size_t)r0 * (EMB * 4);
        asm volatile("mbarrier.arrive.expect_tx.shared::cta.b64 _, [%0], %1;"
                     :: "r"(mb), "r"(bytes) : "memory");
        asm volatile("cp.async.bulk.shared::cta.global.mbarrier::complete_tx::bytes [%0], [%1], %2, [%3];"
                     :: "r"(dst), "l"(sp), "r"(bytes), "r"(mb) : "memory");
    };

    if (t == 0) {
        int pre = nchunks < (NBUF - 1) ? nchunks : (NBUF - 1);
        for (int k = 0; k < pre; ++k) issue(k);
    }

    int c = t % EMB4;            // float4 column
    int p = t / EMB4;            // row parity (t<150)
    int wid = t >> 5, lane = t & 31;
    const float4* __restrict__ W4 = (const float4*)W;
    float4 acc = make_float4(0.f, 0.f, 0.f, 0.f);

    int gi = 0;
    int gstart = 0;
    int nb = g_starts[g0 + 1] - base;

    auto do_finalize = [&](int end_row) {
        int pb = gi & 1;
        float inv = 1.0f / fmaxf((float)(end_row - gstart), 1.0f);
        #pragma unroll
        for (int task = 0; task < TASKS; ++task) {
            float4 w4 = __ldg(&W4[task * EMB4 + c]);
            float pz = acc.x * w4.x + acc.y * w4.y + acc.z * w4.z + acc.w * w4.w;
            #pragma unroll
            for (int o = 16; o; o >>= 1) pz += __shfl_xor_sync(0xffffffffu, pz, o);
            if (lane == 0) sh_warp[pb][wid * TASKS + task] = pz;
        }
        __syncthreads();
        if (t < TASKS) {
            const float* sw = &sh_warp[pb][0];
            float a = sw[t] + sw[TASKS + t] + sw[2 * TASKS + t]
                    + sw[3 * TASKS + t] + sw[4 * TASKS + t];
            out[(size_t)(g0 + gi) * TASKS + t] = a * inv + __ldg(&b[t]);
        }
        acc = make_float4(0.f, 0.f, 0.f, 0.f);
        gstart = end_row;
        ++gi;
        nb = (gi < gcnt) ? g_starts[g0 + gi + 1] - base : 0x7fffffff;
    };

    for (int k = 0; k < nchunks; ++k) {
        int s = k & (NBUF - 1);
        uint32_t mb = mb0 + 8u * s;
        uint32_t ph = (uint32_t)((k >> 2) & 1);

        uint32_t done;
        asm volatile("{\n\t.reg .pred p;\n\t"
                     "mbarrier.try_wait.parity.acquire.cta.shared::cta.b64 p, [%1], %2;\n\t"
                     "selp.b32 %0, 1, 0, p;\n\t}"
                     : "=r"(done) : "r"(mb), "r"(ph) : "memory");
        while (!done) {
            asm volatile("{\n\t.reg .pred p;\n\t"
                         "mbarrier.try_wait.parity.acquire.cta.shared::cta.b64 p, [%1], %2, 0x989680;\n\t"
                         "selp.b32 %0, 1, 0, p;\n\t}"
                         : "=r"(done) : "r"(mb), "r"(ph) : "memory");
        }

        // refill 3-ahead NOW: buffer (k+3)&3 was freed by the sync at the end
        // of iteration k-1 (prologue covered k=0..2 targets fresh buffers).
        if (t == 0 && k + (NBUF - 1) < nchunks) {
            asm volatile("fence.proxy.async.shared::cta;" ::: "memory");
            issue(k + (NBUF - 1));
        }

        int rbase = k * ROWB;
        int rend  = rbase + ROWB; if (rend > rows_total) rend = rows_total;
        const float4* bp = &buf[s][0];

        if (nb >= rend && rend == rbase + ROWB) {
            // fast path: whole (full) chunk inside current graph
            if (t < 150) {
                float4 v0 = bp[(0 + p) * EMB4 + c];
                float4 v1 = bp[(2 + p) * EMB4 + c];
                float4 v2 = bp[(4 + p) * EMB4 + c];
                float4 v3 = bp[(6 + p) * EMB4 + c];
                facc(acc, v0); facc(acc, v1); facc(acc, v2); facc(acc, v3);
            }
        } else {
            int pos = rbase;
            while (pos < rend) {
                int stop = nb < rend ? nb : rend;
                if (t < 150) {
                    for (int r = pos; r < stop; ++r) {
                        if (((r - rbase) & 1) == p)
                            facc(acc, bp[(r - rbase) * EMB4 + c]);
                    }
                }
                if (stop == nb) do_finalize(nb);
                pos = stop;
            }
        }
        __syncthreads();   // chunk s consumed -> its buffer refillable next iter
    }

    // graph whose boundary coincides with the final chunk end is still open
    if (gi < gcnt) do_finalize(rows_total);

    // remaining graphs are empty: mean = 0 -> out = bias
    while (gi < gcnt) {
        if (t < TASKS) out[(size_t)(g0 + gi) * TASKS + t] = __ldg(&b[t]);
        ++gi;
    }
}

// ---------------------------------------------------------------------------
extern "C" void kernel_launch(void* const* d_in, const int* in_sizes, int n_in,
                              void* d_out, int out_size) {
    const float* x     = (const float*)d_in[0];
    const void*  batch = d_in[1];
    const float* W     = (const float*)d_in[2];
    const float* b     = (const float*)d_in[3];
    float*       out   = (float*)d_out;

    int N = in_sizes[1];
    int G = out_size / TASKS;

    int nthreads = (N + 7) / 8;
    starts_kernel<<<(nthreads + 255) / 256, 256>>>(batch, N, G);
    pool_pers_kernel<<<NCTA, THREADS>>>(x, W, b, out, G);
}

// round 11
// speedup vs baseline: 1.0878x; 1.0125x over previous
#include <cuda_runtime.h>
#include <cstdint>

#define EMB     300
#define EMB4    75
#define TASKS   12
#define ROWB    16                      // rows per pipeline chunk (19200 B)
#define NBUF    3
#define THREADS 160                     // 5 warps; 150 loader lanes
#define NCTA    444                     // 3 CTAs/SM x 148 SMs = one wave

__device__ int g_starts[16385 * 2];

// ---------------------------------------------------------------------------
// Vectorized starts fill: each thread handles 8 consecutive batch elements
// (int4 loads). starts[g] = lower_bound(sorted batch, g).
// int32/int64 detected via word[N-1] (int64 high word == 0).
// ---------------------------------------------------------------------------
__global__ void starts_kernel(const void* __restrict__ batch, int N, int G) {
    int base = (blockIdx.x * blockDim.x + threadIdx.x) * 8;
    if (base >= N) return;
    const int* b32 = (const int*)batch;
    bool is64 = (b32[N - 1] == 0);

    int cnt = N - base; if (cnt > 8) cnt = 8;
    int ids[8];
    if (is64) {
        const long long* b64 = (const long long*)batch;
        if (cnt == 8) {
            const int4* p = (const int4*)(b64 + base);
            int4 v0 = p[0], v1 = p[1], v2 = p[2], v3 = p[3];
            ids[0] = v0.x; ids[1] = v0.z; ids[2] = v1.x; ids[3] = v1.z;
            ids[4] = v2.x; ids[5] = v2.z; ids[6] = v3.x; ids[7] = v3.z;
        } else {
            for (int j = 0; j < cnt; ++j) ids[j] = (int)b64[base + j];
        }
    } else {
        if (cnt == 8) {
            const int4* p = (const int4*)(b32 + base);
            int4 v0 = p[0], v1 = p[1];
            ids[0] = v0.x; ids[1] = v0.y; ids[2] = v0.z; ids[3] = v0.w;
            ids[4] = v1.x; ids[5] = v1.y; ids[6] = v1.z; ids[7] = v1.w;
        } else {
            for (int j = 0; j < cnt; ++j) ids[j] = b32[base + j];
        }
    }

    int prev;
    if (base == 0) prev = -1;
    else prev = is64 ? (int)((const long long*)batch)[base - 1] : b32[base - 1];

    #pragma unroll
    for (int j = 0; j < 8; ++j) {
        if (j >= cnt) break;
        int cur = ids[j];
        for (int g = prev + 1; g <= cur; ++g)
            if (g >= 0 && g <= G) g_starts[g] = base + j;
        prev = cur;
    }
    if (base + cnt == N) {
        for (int g = prev + 1; g <= G; ++g) g_starts[g] = N;
    }
}

__device__ __forceinline__ void facc(float4& a, const float4 v) {
    a.x += v.x; a.y += v.y; a.z += v.z; a.w += v.w;
}

// ---------------------------------------------------------------------------
// Persistent single-wave CTA over a contiguous graph range: one continuous
// cp.async.bulk stream, 3-stage ring of 16-row chunks. Finalize: per-thread
// head partial -> warp shfl -> 60-float smem -> ONE sync -> 12 stores.
// Producer refills 2-ahead immediately after each chunk-wait.
// ---------------------------------------------------------------------------
__global__ __launch_bounds__(THREADS)
void pool_pers_kernel(const float* __restrict__ x,
                      const float* __restrict__ W,
                      const float* __restrict__ b,
                      float* __restrict__ out, int G) {
    __shared__ alignas(16) float4 buf[NBUF][ROWB * EMB4];
    __shared__ alignas(8)  unsigned long long mbar[NBUF];
    __shared__ alignas(16) float sh_warp[2][5 * TASKS];

    int t = threadIdx.x;
    int g0 = (int)(((long long)blockIdx.x * G) / NCTA);
    int g1 = (int)(((long long)(blockIdx.x + 1) * G) / NCTA);
    int gcnt = g1 - g0;
    if (gcnt <= 0) return;

    int base       = g_starts[g0];
    int rows_total = g_starts[g1] - base;
    int nchunks    = (rows_total + ROWB - 1) / ROWB;

    uint32_t mb0 = (uint32_t)__cvta_generic_to_shared(&mbar[0]);
    if (t == 0) {
        #pragma unroll
        for (int s = 0; s < NBUF; ++s)
            asm volatile("mbarrier.init.shared::cta.b64 [%0], 1;"
                         :: "r"(mb0 + 8u * s) : "memory");
    }
    __syncthreads();

    const char* src_base = (const char*)(x + (size_t)base * EMB);

    // producer helper: issue chunk kk into ring stage st
    auto issue = [&](int kk, int st) {
        int r0 = kk * ROWB;
        int rc = rows_total - r0; if (rc > ROWB) rc = ROWB;
        uint32_t bytes = (uint32_t)rc * (EMB * 4);
        uint32_t mb    = mb0 + 8u * st;
        uint32_t dst   = (uint32_t)__cvta_generic_to_shared(&buf[st][0]);
        const char* sp = src_base + (size_t)r0 * (EMB * 4);
        asm volatile("mbarrier.arrive.expect_tx.shared::cta.b64 _, [%0], %1;"
                     :: "r"(mb), "r"(bytes) : "memory");
        asm volatile("cp.async.bulk.shared::cta.global.mbarrier::complete_tx::bytes [%0], [%1], %2, [%3];"
                     :: "r"(dst), "l"(sp), "r"(bytes), "r"(mb) : "memory");
    };

    if (t == 0) {
        int pre = nchunks < (NBUF - 1) ? nchunks : (NBUF - 1);
        for (int k = 0; k < pre; ++k) issue(k, k);
    }

    int c = t % EMB4;            // float4 column
    int p = t / EMB4;            // row parity (t<150)
    int wid = t >> 5, lane = t & 31;
    const float4* __restrict__ W4 = (const float4*)W;
    float4 acc = make_float4(0.f, 0.f, 0.f, 0.f);

    int gi = 0;
    int gstart = 0;
    int nb = g_starts[g0 + 1] - base;

    auto do_finalize = [&](int end_row) {
        int pb = gi & 1;
        float inv = 1.0f / fmaxf((float)(end_row - gstart), 1.0f);
        #pragma unroll
        for (int task = 0; task < TASKS; ++task) {
            float4 w4 = __ldg(&W4[task * EMB4 + c]);
            float pz = acc.x * w4.x + acc.y * w4.y + acc.z * w4.z + acc.w * w4.w;
            #pragma unroll
            for (int o = 16; o; o >>= 1) pz += __shfl_xor_sync(0xffffffffu, pz, o);
            if (lane == 0) sh_warp[pb][wid * TASKS + task] = pz;
        }
        __syncthreads();
        if (t < TASKS) {
            const float* sw = &sh_warp[pb][0];
            float a = sw[t] + sw[TASKS + t] + sw[2 * TASKS + t]
                    + sw[3 * TASKS + t] + sw[4 * TASKS + t];
            out[(size_t)(g0 + gi) * TASKS + t] = a * inv + __ldg(&b[t]);
        }
        acc = make_float4(0.f, 0.f, 0.f, 0.f);
        gstart = end_row;
        ++gi;
        nb = (gi < gcnt) ? g_starts[g0 + gi + 1] - base : 0x7fffffff;
    };

    // ring cursors (NBUF=3 is not a power of two -> incremental, no div/mod)
    int cs = 0, cph = 0;                    // consumer stage + phase
    int ps = (NBUF - 1) % NBUF;             // producer stage for chunk k+NBUF-1

    for (int k = 0; k < nchunks; ++k) {
        uint32_t mb = mb0 + 8u * cs;
        uint32_t ph = (uint32_t)cph;

        uint32_t done;
        asm volatile("{\n\t.reg .pred p;\n\t"
                     "mbarrier.try_wait.parity.acquire.cta.shared::cta.b64 p, [%1], %2;\n\t"
                     "selp.b32 %0, 1, 0, p;\n\t}"
                     : "=r"(done) : "r"(mb), "r"(ph) : "memory");
        while (!done) {
            asm volatile("{\n\t.reg .pred p;\n\t"
                         "mbarrier.try_wait.parity.acquire.cta.shared::cta.b64 p, [%1], %2, 0x989680;\n\t"
                         "selp.b32 %0, 1, 0, p;\n\t}"
                         : "=r"(done) : "r"(mb), "r"(ph) : "memory");
        }

        // refill (NBUF-1)-ahead: its target stage was consumed at iter k-1
        // and released by that iteration's trailing __syncthreads.
        if (t == 0 && k + (NBUF - 1) < nchunks) {
            asm volatile("fence.proxy.async.shared::cta;" ::: "memory");
            issue(k + (NBUF - 1), ps);
        }

        int rbase = k * ROWB;
        int rend  = rbase + ROWB; if (rend > rows_total) rend = rows_total;
        const float4* bp = &buf[cs][0];

        if (nb >= rend && rend == rbase + ROWB) {
            // fast path: whole (full) chunk inside current graph
            if (t < 150) {
                #pragma unroll
                for (int r = 0; r < ROWB; r += 2)
                    facc(acc, bp[(r + p) * EMB4 + c]);
            }
        } else {
            int pos = rbase;
            while (pos < rend) {
                int stop = nb < rend ? nb : rend;
                if (t < 150) {
                    for (int r = pos; r < stop; ++r) {
                        if (((r - rbase) & 1) == p)
                            facc(acc, bp[(r - rbase) * EMB4 + c]);
                    }
                }
                if (stop == nb) do_finalize(nb);
                pos = stop;
            }
        }
        __syncthreads();   // stage cs consumed -> refillable next iteration

        if (++cs == NBUF) { cs = 0; cph ^= 1; }
        if (++ps == NBUF) { ps = 0; }
    }

    // graph whose boundary coincides with the final chunk end is still open
    if (gi < gcnt) do_finalize(rows_total);

    // remaining graphs are empty: mean = 0 -> out = bias
    while (gi < gcnt) {
        if (t < TASKS) out[(size_t)(g0 + gi) * TASKS + t] = __ldg(&b[t]);
        ++gi;
    }
}

// ---------------------------------------------------------------------------
extern "C" void kernel_launch(void* const* d_in, const int* in_sizes, int n_in,
                              void* d_out, int out_size) {
    const float* x     = (const float*)d_in[0];
    const void*  batch = d_in[1];
    const float* W     = (const float*)d_in[2];
    const float* b     = (const float*)d_in[3];
    float*       out   = (float*)d_out;

    int N = in_sizes[1];
    int G = out_size / TASKS;

    int nthreads = (N + 7) / 8;
    starts_kernel<<<(nthreads + 255) / 256, 256>>>(batch, N, G);
    pool_pers_kernel<<<NCTA, THREADS>>>(x, W, b, out, G);
}